// round 2
// baseline (speedup 1.0000x reference)
#include <cuda_runtime.h>
#include <cstdint>

#define KK 64

// per-batch log-likelihood scratch (no cudaMalloc allowed)
__device__ float g_ll[4096];

__device__ __forceinline__ float fast_rcp(float x) {
    float r; asm("rcp.approx.f32 %0, %1;" : "=f"(r) : "f"(x)); return r;
}

__device__ __forceinline__ uint32_t smem_u32(const void* p) {
    uint32_t a;
    asm("{ .reg .u64 t; cvta.to.shared.u64 t, %1; cvt.u32.u64 %0, t; }"
        : "=r"(a) : "l"(p));
    return a;
}

// One block per batch element. 64 threads; thread j owns state j.
// Forward recursion in scaled-exp domain with packed f32x2 dot products:
//   u_t = (u_{t-1} . M) * exp(emit_t)            (M = exp(transition), col j in regs)
//   every 4th step:  u /= u[0],  C += log(u[0])
//   log_Z = C + log(sum_j u_T[j])
__global__ __launch_bounds__(KK) void crf_forward_kernel(
    const int* __restrict__ y, const float* __restrict__ em,
    const float* __restrict__ tr, int Tn)
{
    __shared__ __align__(16) float u_sh[2 * KK];
    __shared__ int y_sh[1024];          // T = 1024 for this problem
    __shared__ float red2[2];

    const int b = blockIdx.x;
    const int j = threadIdx.x;
    const int* yb = y + (size_t)b * Tn;
    const float* eb = em + (size_t)b * Tn * KK;

    // Packed M column for state j: Mp[q] = (exp(tr[2q][j]), exp(tr[2q+1][j]))
    unsigned long long Mp[KK / 2];
#pragma unroll
    for (int q = 0; q < KK / 2; q++) {
        float m0 = __expf(tr[(2 * q) * KK + j]);
        float m1 = __expf(tr[(2 * q + 1) * KK + j]);
        asm("mov.b64 %0, {%1, %2};" : "=l"(Mp[q]) : "f"(m0), "f"(m1));
    }

    // stage y row in shared
    for (int t = j; t < Tn; t += KK) y_sh[t] = yb[t];

    // alpha0 = emissions[:,0,:]  ->  u = exp(alpha0), C = 0
    u_sh[j] = __expf(eb[j]);
    float C = 0.f;
    int p = 0;
    __syncthreads();

    const uint32_t ubase = smem_u32(u_sh);

    auto step = [&](float ecur, int tt) {
        int yt = y_sh[tt];
        if (yt != 0) {                       // uniform across block
            float ex = __expf(ecur);         // off the u-dependency chain
            uint32_t ua = ubase + (p << 8);  // p * 64 floats * 4B
            unsigned long long a0 = 0, a1 = 0, a2 = 0, a3 = 0;
#pragma unroll
            for (int q = 0; q < 8; q++) {
                unsigned long long p0, p1, p2, p3;
                asm("ld.shared.v2.u64 {%0, %1}, [%2];"
                    : "=l"(p0), "=l"(p1) : "r"(ua + q * 32));
                asm("ld.shared.v2.u64 {%0, %1}, [%2];"
                    : "=l"(p2), "=l"(p3) : "r"(ua + q * 32 + 16));
                asm("fma.rn.f32x2 %0, %1, %2, %0;" : "+l"(a0) : "l"(p0), "l"(Mp[4 * q + 0]));
                asm("fma.rn.f32x2 %0, %1, %2, %0;" : "+l"(a1) : "l"(p1), "l"(Mp[4 * q + 1]));
                asm("fma.rn.f32x2 %0, %1, %2, %0;" : "+l"(a2) : "l"(p2), "l"(Mp[4 * q + 2]));
                asm("fma.rn.f32x2 %0, %1, %2, %0;" : "+l"(a3) : "l"(p3), "l"(Mp[4 * q + 3]));
            }
            asm("add.rn.f32x2 %0, %0, %1;" : "+l"(a0) : "l"(a1));
            asm("add.rn.f32x2 %0, %0, %1;" : "+l"(a2) : "l"(a3));
            asm("add.rn.f32x2 %0, %0, %1;" : "+l"(a0) : "l"(a2));
            float lo, hi;
            asm("mov.b64 {%0, %1}, %2;" : "=f"(lo), "=f"(hi) : "l"(a0));
            float x = (lo + hi) * ex;

            if ((tt & 3) == 0) {             // periodic rescale (uniform)
                float x0 = u_sh[p * KK];
                x *= fast_rcp(x0);
                C += __logf(x0);
            }
            u_sh[(p ^ 1) * KK + j] = x;
            __syncthreads();
            p ^= 1;
        }
    };

    // software-pipelined emissions prefetch, depth 4
    int lim = Tn - 1;
    float e0 = eb[(size_t)min(1, lim) * KK + j];
    float e1 = eb[(size_t)min(2, lim) * KK + j];
    float e2 = eb[(size_t)min(3, lim) * KK + j];
    float e3 = eb[(size_t)min(4, lim) * KK + j];

    int t = 1;
    for (; t + 3 <= lim; t += 4) {
        int i0 = min(t + 4, lim), i1 = min(t + 5, lim);
        int i2 = min(t + 6, lim), i3 = min(t + 7, lim);
        float n0 = eb[(size_t)i0 * KK + j];
        float n1 = eb[(size_t)i1 * KK + j];
        float n2 = eb[(size_t)i2 * KK + j];
        float n3 = eb[(size_t)i3 * KK + j];
        step(e0, t); step(e1, t + 1); step(e2, t + 2); step(e3, t + 3);
        e0 = n0; e1 = n1; e2 = n2; e3 = n3;
    }
    for (; t <= lim; t++) { step(e0, t); e0 = e1; e1 = e2; e2 = e3; }

    __syncthreads();

    // log_Z = C + log(sum u)    (redundant per-thread; identical result)
    float s = 0.f;
    const float4* uf = reinterpret_cast<const float4*>(u_sh + p * KK);
#pragma unroll
    for (int q = 0; q < KK / 4; q++) {
        float4 uu = uf[q];
        s += (uu.x + uu.y) + (uu.z + uu.w);
    }
    float logz = C + __logf(s);

    // numerator: emission + transition scores along the gold path (masked)
    float num = 0.f;
    for (int tt = j; tt < Tn; tt += KK) {
        int yt = y_sh[tt];
        if (yt != 0) {
            num += eb[(size_t)tt * KK + yt];
            if (tt > 0) num += tr[y_sh[tt - 1] * KK + yt];
        }
    }
#pragma unroll
    for (int o = 16; o > 0; o >>= 1) num += __shfl_xor_sync(0xffffffffu, num, o);
    if ((j & 31) == 0) red2[j >> 5] = num;
    __syncthreads();
    if (j == 0) g_ll[b] = (red2[0] + red2[1]) - logz;
}

__global__ void crf_finalize(float* __restrict__ out, int B)
{
    __shared__ float sh[8];
    int tid = threadIdx.x;
    float v = 0.f;
    for (int i = tid; i < B; i += blockDim.x) v += g_ll[i];
#pragma unroll
    for (int o = 16; o > 0; o >>= 1) v += __shfl_xor_sync(0xffffffffu, v, o);
    if ((tid & 31) == 0) sh[tid >> 5] = v;
    __syncthreads();
    if (tid == 0) {
        float s = 0.f;
#pragma unroll
        for (int w = 0; w < 8; w++) s += sh[w];
        out[0] = -s / (float)B;
    }
}

extern "C" void kernel_launch(void* const* d_in, const int* in_sizes, int n_in,
                              void* d_out, int out_size)
{
    const int*   y  = (const int*)d_in[0];
    const float* em = (const float*)d_in[1];
    const float* tr = (const float*)d_in[2];

    const int Tn = 1024;                 // problem shape: B=256, T=1024, K=64
    const int B  = in_sizes[0] / Tn;

    crf_forward_kernel<<<B, KK>>>(y, em, tr, Tn);
    crf_finalize<<<1, 256>>>((float*)d_out, B);
}

// round 3
// speedup vs baseline: 1.2155x; 1.2155x over previous
#include <cuda_runtime.h>
#include <cstdint>

#define KK 64

// per-batch log-likelihood scratch (no cudaMalloc allowed)
__device__ float g_ll[4096];

__device__ __forceinline__ float fast_rcp(float x) {
    float r; asm("rcp.approx.f32 %0, %1;" : "=f"(r) : "f"(x)); return r;
}

__device__ __forceinline__ uint32_t smem_u32(const void* p) {
    uint32_t a;
    asm("{ .reg .u64 t; cvta.to.shared.u64 t, %1; cvt.u32.u64 %0, t; }"
        : "=r"(a) : "l"(p));
    return a;
}

// ONE WARP PER BATCH. 32 lanes; lane l owns states (2l, 2l+1).
// No cross-warp sync anywhere in the hot loop — only __syncwarp.
// Scaled-exp domain recursion with packed f32x2 dot products:
//   u_t = (u_{t-1} . M) * exp(emit_t)      (M = exp(transition))
//   every 4th step:  u *= 1/u[0],  C += log(u[0])
//   log_Z = C + log(sum_j u_T[j])
__global__ __launch_bounds__(64, 1) void crf_forward_kernel(
    const int* __restrict__ y, const float* __restrict__ em,
    const float* __restrict__ tr, int Tn)
{
    __shared__ __align__(16) float u_sh[2][2][KK];   // [warp][buf][state]
    __shared__ int y_sh[2][1024];                    // T = 1024

    const int w = threadIdx.x >> 5;      // warp in block = batch slot
    const int l = threadIdx.x & 31;
    const int b = blockIdx.x * 2 + w;
    const int s0 = 2 * l;
    const int* yb = y + (size_t)b * Tn;
    const float* eb = em + (size_t)b * Tn * KK;

    // Packed M rows for this lane's two output states:
    //   Ma[q] = (exp(tr[2q][s0]),   exp(tr[2q+1][s0]))
    //   Mb[q] = (exp(tr[2q][s0+1]), exp(tr[2q+1][s0+1]))
    unsigned long long Ma[32], Mb[32];
#pragma unroll
    for (int q = 0; q < 32; q++) {
        float a0 = __expf(tr[(2 * q) * KK + s0]);
        float a1 = __expf(tr[(2 * q + 1) * KK + s0]);
        float b0 = __expf(tr[(2 * q) * KK + s0 + 1]);
        float b1 = __expf(tr[(2 * q + 1) * KK + s0 + 1]);
        asm("mov.b64 %0, {%1, %2};" : "=l"(Ma[q]) : "f"(a0), "f"(a1));
        asm("mov.b64 %0, {%1, %2};" : "=l"(Mb[q]) : "f"(b0), "f"(b1));
    }

    // stage y row in shared (per warp)
    for (int t = l; t < Tn; t += 32) y_sh[w][t] = yb[t];

    // u0 = exp(emissions[b,0,:])
    {
        float2 e00 = *reinterpret_cast<const float2*>(eb + s0);
        float2 u0;
        u0.x = __expf(e00.x);
        u0.y = __expf(e00.y);
        *reinterpret_cast<float2*>(&u_sh[w][0][s0]) = u0;
    }
    float C = 0.f;
    int p = 0;
    __syncwarp();

    const uint32_t ubase = smem_u32(&u_sh[w][0][0]);

    auto step = [&](float2 ecur, int tt) {
        int yt = y_sh[w][tt];
        if (yt != 0) {                        // warp-uniform branch
            float ex0 = __expf(ecur.x);       // off the u-dependency chain
            float ex1 = __expf(ecur.y);
            float scale = 1.f;
            if ((tt & 3) == 0) {              // periodic rescale (uniform)
                float x0 = u_sh[w][p][0];     // broadcast LDS, issued early
                scale = fast_rcp(x0);
                C += __logf(x0);
            }
            const uint32_t ua = ubase + (p << 8);   // p * 64 floats * 4B
            unsigned long long A[4] = {0, 0, 0, 0};
            unsigned long long B[4] = {0, 0, 0, 0};
#pragma unroll
            for (int g = 0; g < 16; g++) {
                unsigned long long p0, p1;    // pairs (u[4g],u[4g+1]), (u[4g+2],u[4g+3])
                asm("ld.shared.v2.u64 {%0, %1}, [%2];"
                    : "=l"(p0), "=l"(p1) : "r"(ua + g * 16));
                const int i0 = (g & 1) * 2, i1 = i0 + 1;
                asm("fma.rn.f32x2 %0, %1, %2, %0;" : "+l"(A[i0]) : "l"(p0), "l"(Ma[2 * g]));
                asm("fma.rn.f32x2 %0, %1, %2, %0;" : "+l"(A[i1]) : "l"(p1), "l"(Ma[2 * g + 1]));
                asm("fma.rn.f32x2 %0, %1, %2, %0;" : "+l"(B[i0]) : "l"(p0), "l"(Mb[2 * g]));
                asm("fma.rn.f32x2 %0, %1, %2, %0;" : "+l"(B[i1]) : "l"(p1), "l"(Mb[2 * g + 1]));
            }
            asm("add.rn.f32x2 %0, %0, %1;" : "+l"(A[0]) : "l"(A[2]));
            asm("add.rn.f32x2 %0, %0, %1;" : "+l"(A[1]) : "l"(A[3]));
            asm("add.rn.f32x2 %0, %0, %1;" : "+l"(A[0]) : "l"(A[1]));
            asm("add.rn.f32x2 %0, %0, %1;" : "+l"(B[0]) : "l"(B[2]));
            asm("add.rn.f32x2 %0, %0, %1;" : "+l"(B[1]) : "l"(B[3]));
            asm("add.rn.f32x2 %0, %0, %1;" : "+l"(B[0]) : "l"(B[1]));
            float a_lo, a_hi, b_lo, b_hi;
            asm("mov.b64 {%0, %1}, %2;" : "=f"(a_lo), "=f"(a_hi) : "l"(A[0]));
            asm("mov.b64 {%0, %1}, %2;" : "=f"(b_lo), "=f"(b_hi) : "l"(B[0]));
            float2 dd;
            dd.x = (a_lo + a_hi) * (ex0 * scale);
            dd.y = (b_lo + b_hi) * (ex1 * scale);
            *reinterpret_cast<float2*>(&u_sh[w][p ^ 1][s0]) = dd;
            __syncwarp();
            p ^= 1;
        }
    };

    // software-pipelined emissions prefetch, depth 4 (float2 per lane)
    const int lim = Tn - 1;
    const float2* eb2 = reinterpret_cast<const float2*>(eb + s0);
    auto eld = [&](int t) { return *reinterpret_cast<const float2*>(eb + (size_t)t * KK + s0); };
    float2 e0 = eld(min(1, lim));
    float2 e1 = eld(min(2, lim));
    float2 e2 = eld(min(3, lim));
    float2 e3 = eld(min(4, lim));
    (void)eb2;

    int t = 1;
    for (; t + 3 <= lim; t += 4) {
        float2 n0 = eld(min(t + 4, lim));
        float2 n1 = eld(min(t + 5, lim));
        float2 n2 = eld(min(t + 6, lim));
        float2 n3 = eld(min(t + 7, lim));
        step(e0, t); step(e1, t + 1); step(e2, t + 2); step(e3, t + 3);
        e0 = n0; e1 = n1; e2 = n2; e3 = n3;
    }
    for (; t <= lim; t++) { step(e0, t); e0 = e1; e1 = e2; e2 = e3; }

    __syncwarp();

    // log_Z = C + log(sum u)   (redundant per-lane; identical result)
    float s = 0.f;
    const float4* uf = reinterpret_cast<const float4*>(&u_sh[w][p][0]);
#pragma unroll
    for (int q = 0; q < KK / 4; q++) {
        float4 uu = uf[q];
        s += (uu.x + uu.y) + (uu.z + uu.w);
    }
    float logz = C + __logf(s);

    // numerator: emission + transition scores along the gold path (masked)
    float num = 0.f;
    for (int tt = l; tt < Tn; tt += 32) {
        int yt = y_sh[w][tt];
        if (yt != 0) {
            num += eb[(size_t)tt * KK + yt];
            if (tt > 0) num += tr[y_sh[w][tt - 1] * KK + yt];
        }
    }
#pragma unroll
    for (int o = 16; o > 0; o >>= 1) num += __shfl_xor_sync(0xffffffffu, num, o);
    if (l == 0) g_ll[b] = num - logz;
}

__global__ void crf_finalize(float* __restrict__ out, int B)
{
    __shared__ float sh[8];
    int tid = threadIdx.x;
    float v = 0.f;
    for (int i = tid; i < B; i += blockDim.x) v += g_ll[i];
#pragma unroll
    for (int o = 16; o > 0; o >>= 1) v += __shfl_xor_sync(0xffffffffu, v, o);
    if ((tid & 31) == 0) sh[tid >> 5] = v;
    __syncthreads();
    if (tid == 0) {
        float s = 0.f;
#pragma unroll
        for (int w = 0; w < 8; w++) s += sh[w];
        out[0] = -s / (float)B;
    }
}

extern "C" void kernel_launch(void* const* d_in, const int* in_sizes, int n_in,
                              void* d_out, int out_size)
{
    const int*   y  = (const int*)d_in[0];
    const float* em = (const float*)d_in[1];
    const float* tr = (const float*)d_in[2];

    const int Tn = 1024;                 // problem shape: B=256, T=1024, K=64
    const int B  = in_sizes[0] / Tn;

    crf_forward_kernel<<<B / 2, 64>>>(y, em, tr, Tn);
    crf_finalize<<<1, 256>>>((float*)d_out, B);
}

// round 6
// speedup vs baseline: 1.5093x; 1.2418x over previous
#include <cuda_runtime.h>
#include <cstdint>

#define KK 64

// per-batch log-likelihood scratch (no cudaMalloc allowed)
__device__ float g_ll[4096];

__device__ __forceinline__ float fast_rcp(float x) {
    float r; asm("rcp.approx.f32 %0, %1;" : "=f"(r) : "f"(x)); return r;
}

__device__ __forceinline__ uint32_t smem_u32(const void* p) {
    uint32_t a;
    asm("{ .reg .u64 t; cvta.to.shared.u64 t, %1; cvt.u32.u64 %0, t; }"
        : "=r"(a) : "l"(p));
    return a;
}

// ONE WARP PER BATCH. 32 lanes; lane l owns states (2l, 2l+1).
// Branchless scaled-exp recursion, packed f32x2 dots, compile-time parity:
//   u_t = (u_{t-1} . M) * exp(emit_t)        (masked steps: u_t = u_{t-1})
//   every 8th step (unconditional): u *= 1/u[0], C += log(u[0])
//   log_Z = C + log(sum_j u_T[j])
__global__ __launch_bounds__(64, 1) void crf_forward_kernel(
    const int* __restrict__ y, const float* __restrict__ em,
    const float* __restrict__ tr, int Tn)
{
    __shared__ __align__(16) float u_sh[2][2][KK];   // [warp][buf][state]
    __shared__ int y_sh[2][1024];                    // T = 1024

    const int w = threadIdx.x >> 5;      // warp in block = batch slot
    const int l = threadIdx.x & 31;
    const int b = blockIdx.x * 2 + w;
    const int s0 = 2 * l;
    const int* yb = y + (size_t)b * Tn;
    const float* eb = em + (size_t)b * Tn * KK;

    // Packed M rows for this lane's two output states
    unsigned long long Ma[32], Mb[32];
#pragma unroll
    for (int q = 0; q < 32; q++) {
        float a0 = __expf(tr[(2 * q) * KK + s0]);
        float a1 = __expf(tr[(2 * q + 1) * KK + s0]);
        float b0 = __expf(tr[(2 * q) * KK + s0 + 1]);
        float b1 = __expf(tr[(2 * q + 1) * KK + s0 + 1]);
        asm("mov.b64 %0, {%1, %2};" : "=l"(Ma[q]) : "f"(a0), "f"(a1));
        asm("mov.b64 %0, {%1, %2};" : "=l"(Mb[q]) : "f"(b0), "f"(b1));
    }

    // stage y row in shared (per warp)
    for (int t = l; t < Tn; t += 32) y_sh[w][t] = yb[t];

    // u0 = exp(emissions[b,0,:]); keep own pair in regs too
    float2 uown;
    {
        float2 e00 = *reinterpret_cast<const float2*>(eb + s0);
        uown.x = __expf(e00.x);
        uown.y = __expf(e00.y);
        *reinterpret_cast<float2*>(&u_sh[w][0][s0]) = uown;
    }
    float C = 0.f;
    __syncwarp();

    // NOTE: ubase is already warp-offset — do NOT add a warp term again.
    const uint32_t ubase = smem_u32(&u_sh[w][0][0]);
    const float* ep = eb + s0;

    // One recursion step. PSRC/RESC are compile-time in the hot loop.
    // Branchless: masked steps commit uown (times sc) instead of the dot.
    // The shared loads MUST be asm volatile: with compile-time psrc the
    // unrolled bodies are textually identical and non-volatile asm gets CSE'd
    // across steps (stale u reads) — that was the R4/R5 correctness bug.
    auto step = [&](float2 ecur, int tt, int psrc, bool resc) {
        const int yt = y_sh[w][tt];
        float ex0 = __expf(ecur.x);
        float ex1 = __expf(ecur.y);
        float sc = 1.f;
        if (resc) {                       // unconditional rescale (valid always)
            float x0 = u_sh[w][psrc][0];  // broadcast LDS
            sc = fast_rcp(x0);
            C += __logf(x0);
        }
        const uint32_t ua = ubase + (psrc << 8);   // buf stride = 64 floats
        unsigned long long A[4] = {0, 0, 0, 0};
        unsigned long long B[4] = {0, 0, 0, 0};
#pragma unroll
        for (int g = 0; g < 16; g++) {
            unsigned long long p0, p1;    // (u[4g],u[4g+1]), (u[4g+2],u[4g+3])
            asm volatile("ld.shared.v2.u64 {%0, %1}, [%2];"
                : "=l"(p0), "=l"(p1) : "r"(ua + g * 16));
            const int i0 = (g & 1) * 2, i1 = i0 + 1;
            asm("fma.rn.f32x2 %0, %1, %2, %0;" : "+l"(A[i0]) : "l"(p0), "l"(Ma[2 * g]));
            asm("fma.rn.f32x2 %0, %1, %2, %0;" : "+l"(A[i1]) : "l"(p1), "l"(Ma[2 * g + 1]));
            asm("fma.rn.f32x2 %0, %1, %2, %0;" : "+l"(B[i0]) : "l"(p0), "l"(Mb[2 * g]));
            asm("fma.rn.f32x2 %0, %1, %2, %0;" : "+l"(B[i1]) : "l"(p1), "l"(Mb[2 * g + 1]));
        }
        asm("add.rn.f32x2 %0, %0, %1;" : "+l"(A[0]) : "l"(A[2]));
        asm("add.rn.f32x2 %0, %0, %1;" : "+l"(A[1]) : "l"(A[3]));
        asm("add.rn.f32x2 %0, %0, %1;" : "+l"(A[0]) : "l"(A[1]));
        asm("add.rn.f32x2 %0, %0, %1;" : "+l"(B[0]) : "l"(B[2]));
        asm("add.rn.f32x2 %0, %0, %1;" : "+l"(B[1]) : "l"(B[3]));
        asm("add.rn.f32x2 %0, %0, %1;" : "+l"(B[0]) : "l"(B[1]));
        float a_lo, a_hi, b_lo, b_hi;
        asm("mov.b64 {%0, %1}, %2;" : "=f"(a_lo), "=f"(a_hi) : "l"(A[0]));
        asm("mov.b64 {%0, %1}, %2;" : "=f"(b_lo), "=f"(b_hi) : "l"(B[0]));
        float dx = (a_lo + a_hi) * (ex0 * sc);
        float dy = (b_lo + b_hi) * (ex1 * sc);
        // branchless commit (no BSSY/BSYNC in the hot loop)
        uown.x = (yt != 0) ? dx : uown.x * sc;
        uown.y = (yt != 0) ? dy : uown.y * sc;
        *reinterpret_cast<float2*>(&u_sh[w][psrc ^ 1][s0]) = uown;
        __syncwarp();
    };

    const int lim = Tn - 1;               // 1023
    auto eld = [&](int t) {
        return *reinterpret_cast<const float2*>(ep + (size_t)t * KK);
    };

    // prefetch rows t .. t+7 (no clamps needed: lim >= 8 here)
    float2 e0 = eld(1), e1 = eld(2), e2 = eld(3), e3 = eld(4);
    float2 e4 = eld(5), e5 = eld(6), e6 = eld(7), e7 = eld(8);

    int t = 1;
    // main loop: t ≡ 1 (mod 8); parity at entry is always 0; rescale at t+7 (≡0 mod 8)
    for (; t + 15 <= lim; t += 8) {
        float2 n0 = eld(t + 8),  n1 = eld(t + 9),  n2 = eld(t + 10), n3 = eld(t + 11);
        float2 n4 = eld(t + 12), n5 = eld(t + 13), n6 = eld(t + 14), n7 = eld(t + 15);
        step(e0, t,     0, false);
        step(e1, t + 1, 1, false);
        step(e2, t + 2, 0, false);
        step(e3, t + 3, 1, false);
        step(e4, t + 4, 0, false);
        step(e5, t + 5, 1, false);
        step(e6, t + 6, 0, false);
        step(e7, t + 7, 1, true);
        e0 = n0; e1 = n1; e2 = n2; e3 = n3;
        e4 = n4; e5 = n5; e6 = n6; e7 = n7;
    }

    // tail: runtime parity / rescale; shift-register prefetch with clamped loads
    int p = 0;                             // (t-1) is a multiple of 8 here
    for (; t <= lim; t++) {
        float2 nn = eld(min(t + 8, lim));
        step(e0, t, p, (t & 7) == 0);
        p ^= 1;
        e0 = e1; e1 = e2; e2 = e3; e3 = e4;
        e4 = e5; e5 = e6; e6 = e7; e7 = nn;
    }
    // final buffer parity: lim steps total from parity 0
    const int pf = lim & 1;

    __syncwarp();

    // log_Z = C + log(sum u)   (redundant per-lane; identical result)
    float s = 0.f;
    const float4* uf = reinterpret_cast<const float4*>(&u_sh[w][pf][0]);
#pragma unroll
    for (int q = 0; q < KK / 4; q++) {
        float4 uu = uf[q];
        s += (uu.x + uu.y) + (uu.z + uu.w);
    }
    float logz = C + __logf(s);

    // numerator: emission + transition scores along the gold path (masked)
    float num = 0.f;
    for (int tt = l; tt < Tn; tt += 32) {
        int yt = y_sh[w][tt];
        if (yt != 0) {
            num += eb[(size_t)tt * KK + yt];
            if (tt > 0) num += tr[y_sh[w][tt - 1] * KK + yt];
        }
    }
#pragma unroll
    for (int o = 16; o > 0; o >>= 1) num += __shfl_xor_sync(0xffffffffu, num, o);
    if (l == 0) g_ll[b] = num - logz;
}

__global__ void crf_finalize(float* __restrict__ out, int B)
{
    __shared__ float sh[8];
    int tid = threadIdx.x;
    float v = 0.f;
    for (int i = tid; i < B; i += blockDim.x) v += g_ll[i];
#pragma unroll
    for (int o = 16; o > 0; o >>= 1) v += __shfl_xor_sync(0xffffffffu, v, o);
    if ((tid & 31) == 0) sh[tid >> 5] = v;
    __syncthreads();
    if (tid == 0) {
        float s = 0.f;
#pragma unroll
        for (int w = 0; w < 8; w++) s += sh[w];
        out[0] = -s / (float)B;
    }
}

extern "C" void kernel_launch(void* const* d_in, const int* in_sizes, int n_in,
                              void* d_out, int out_size)
{
    const int*   y  = (const int*)d_in[0];
    const float* em = (const float*)d_in[1];
    const float* tr = (const float*)d_in[2];

    const int Tn = 1024;                 // problem shape: B=256, T=1024, K=64
    const int B  = in_sizes[0] / Tn;

    crf_forward_kernel<<<B / 2, 64>>>(y, em, tr, Tn);
    crf_finalize<<<1, 256>>>((float*)d_out, B);
}

// round 7
// speedup vs baseline: 1.5360x; 1.0177x over previous
#include <cuda_runtime.h>
#include <cstdint>

#define KK 64

// per-batch log-likelihood scratch (no cudaMalloc allowed)
__device__ float g_ll[4096];

__device__ __forceinline__ float fast_rcp(float x) {
    float r; asm("rcp.approx.f32 %0, %1;" : "=f"(r) : "f"(x)); return r;
}

__device__ __forceinline__ uint32_t smem_u32(const void* p) {
    uint32_t a;
    asm("{ .reg .u64 t; cvta.to.shared.u64 t, %1; cvt.u32.u64 %0, t; }"
        : "=r"(a) : "l"(p));
    return a;
}

// ONE WARP PER BATCH. 32 lanes; lane l owns states (2l, 2l+1).
// Branchless scaled-exp recursion, packed f32x2 dots, compile-time parity.
// NO per-step __syncwarp: the hot loop is straight-line (statically converged
// warp), and all cross-lane smem traffic is volatile asm (STS commit, LDS
// reads) so both compiler order and per-warp in-order LSU order hold.
//   u_t = (u_{t-1} . M) * exp(emit_t)        (masked steps: u_t = u_{t-1})
//   every 8th step (unconditional): u *= 1/u[0], C += log(u[0])
//   log_Z = C + log(sum_j u_T[j])
__global__ __launch_bounds__(64, 1) void crf_forward_kernel(
    const int* __restrict__ y, const float* __restrict__ em,
    const float* __restrict__ tr, int Tn)
{
    __shared__ __align__(16) float u_sh[2][2][KK];   // [warp][buf][state]
    __shared__ int y_sh[2][1024];                    // T = 1024

    const int w = threadIdx.x >> 5;      // warp in block = batch slot
    const int l = threadIdx.x & 31;
    const int b = blockIdx.x * 2 + w;
    const int s0 = 2 * l;
    const int* yb = y + (size_t)b * Tn;
    const float* eb = em + (size_t)b * Tn * KK;

    // Packed M rows for this lane's two output states
    unsigned long long Ma[32], Mb[32];
#pragma unroll
    for (int q = 0; q < 32; q++) {
        float a0 = __expf(tr[(2 * q) * KK + s0]);
        float a1 = __expf(tr[(2 * q + 1) * KK + s0]);
        float b0 = __expf(tr[(2 * q) * KK + s0 + 1]);
        float b1 = __expf(tr[(2 * q + 1) * KK + s0 + 1]);
        asm("mov.b64 %0, {%1, %2};" : "=l"(Ma[q]) : "f"(a0), "f"(a1));
        asm("mov.b64 %0, {%1, %2};" : "=l"(Mb[q]) : "f"(b0), "f"(b1));
    }

    // stage y row in shared (per warp)
    for (int t = l; t < Tn; t += 32) y_sh[w][t] = yb[t];

    // u0 = exp(emissions[b,0,:]); keep own pair in regs too
    float2 uown;
    {
        float2 e00 = *reinterpret_cast<const float2*>(eb + s0);
        uown.x = __expf(e00.x);
        uown.y = __expf(e00.y);
        *reinterpret_cast<float2*>(&u_sh[w][0][s0]) = uown;
    }
    float C = 0.f;
    __syncwarp();

    // ubase is already warp-offset; lane store address base hoisted once.
    const uint32_t ubase = smem_u32(&u_sh[w][0][0]);
    const uint32_t ustore = ubase + (uint32_t)(l << 3);   // + s0*4 bytes
    const float* ep = eb + s0;

    // One recursion step. PSRC/RESC are compile-time in the hot loop.
    // Shared loads/stores are asm volatile: prevents cross-step CSE (the R4/R5
    // bug) AND provides the ordering that lets us drop the per-step syncwarp.
    auto step = [&](float2 ecur, int tt, int psrc, bool resc) {
        const int yt = y_sh[w][tt];
        float ex0 = __expf(ecur.x);
        float ex1 = __expf(ecur.y);
        float sc = 1.f;
        if (resc) {                       // unconditional rescale (valid always)
            float x0;
            asm volatile("ld.shared.f32 %0, [%1];"
                         : "=f"(x0) : "r"(ubase + (uint32_t)(psrc << 8)));
            sc = fast_rcp(x0);
            C += __logf(x0);
        }
        const float k0 = ex0 * sc;        // off the u-dependency chain
        const float k1 = ex1 * sc;
        const uint32_t ua = ubase + (uint32_t)(psrc << 8);
        unsigned long long A[4] = {0, 0, 0, 0};
        unsigned long long B[4] = {0, 0, 0, 0};
#pragma unroll
        for (int g = 0; g < 16; g++) {
            unsigned long long p0, p1;    // (u[4g],u[4g+1]), (u[4g+2],u[4g+3])
            asm volatile("ld.shared.v2.u64 {%0, %1}, [%2];"
                : "=l"(p0), "=l"(p1) : "r"(ua + g * 16));
            const int i0 = (g & 1) * 2, i1 = i0 + 1;
            asm("fma.rn.f32x2 %0, %1, %2, %0;" : "+l"(A[i0]) : "l"(p0), "l"(Ma[2 * g]));
            asm("fma.rn.f32x2 %0, %1, %2, %0;" : "+l"(A[i1]) : "l"(p1), "l"(Ma[2 * g + 1]));
            asm("fma.rn.f32x2 %0, %1, %2, %0;" : "+l"(B[i0]) : "l"(p0), "l"(Mb[2 * g]));
            asm("fma.rn.f32x2 %0, %1, %2, %0;" : "+l"(B[i1]) : "l"(p1), "l"(Mb[2 * g + 1]));
        }
        asm("add.rn.f32x2 %0, %0, %1;" : "+l"(A[0]) : "l"(A[2]));
        asm("add.rn.f32x2 %0, %0, %1;" : "+l"(A[1]) : "l"(A[3]));
        asm("add.rn.f32x2 %0, %0, %1;" : "+l"(A[0]) : "l"(A[1]));
        asm("add.rn.f32x2 %0, %0, %1;" : "+l"(B[0]) : "l"(B[2]));
        asm("add.rn.f32x2 %0, %0, %1;" : "+l"(B[1]) : "l"(B[3]));
        asm("add.rn.f32x2 %0, %0, %1;" : "+l"(B[0]) : "l"(B[1]));
        float a_lo, a_hi, b_lo, b_hi;
        asm("mov.b64 {%0, %1}, %2;" : "=f"(a_lo), "=f"(a_hi) : "l"(A[0]));
        asm("mov.b64 {%0, %1}, %2;" : "=f"(b_lo), "=f"(b_hi) : "l"(B[0]));
        float dx = (a_lo + a_hi) * k0;
        float dy = (b_lo + b_hi) * k1;
        // branchless commit (no BSSY/BSYNC in the hot loop)
        uown.x = (yt != 0) ? dx : uown.x * sc;
        uown.y = (yt != 0) ? dy : uown.y * sc;
        asm volatile("st.shared.v2.f32 [%0], {%1, %2};"
                     :: "r"(ustore + (uint32_t)((psrc ^ 1) << 8)),
                        "f"(uown.x), "f"(uown.y));
    };

    const int lim = Tn - 1;               // 1023
    auto eld = [&](int t) {
        return *reinterpret_cast<const float2*>(ep + (size_t)t * KK);
    };

    // prefetch rows t .. t+7 (no clamps needed: lim >= 8 here)
    float2 e0 = eld(1), e1 = eld(2), e2 = eld(3), e3 = eld(4);
    float2 e4 = eld(5), e5 = eld(6), e6 = eld(7), e7 = eld(8);

    int t = 1;
    // main loop: t ≡ 1 (mod 8); parity at entry is always 0; rescale at t+7 (≡0 mod 8)
    for (; t + 15 <= lim; t += 8) {
        float2 n0 = eld(t + 8),  n1 = eld(t + 9),  n2 = eld(t + 10), n3 = eld(t + 11);
        float2 n4 = eld(t + 12), n5 = eld(t + 13), n6 = eld(t + 14), n7 = eld(t + 15);
        step(e0, t,     0, false);
        step(e1, t + 1, 1, false);
        step(e2, t + 2, 0, false);
        step(e3, t + 3, 1, false);
        step(e4, t + 4, 0, false);
        step(e5, t + 5, 1, false);
        step(e6, t + 6, 0, false);
        step(e7, t + 7, 1, true);
        e0 = n0; e1 = n1; e2 = n2; e3 = n3;
        e4 = n4; e5 = n5; e6 = n6; e7 = n7;
    }

    // tail: runtime parity / rescale; shift-register prefetch with clamped loads
    int p = 0;                             // (t-1) is a multiple of 8 here
    for (; t <= lim; t++) {
        float2 nn = eld(min(t + 8, lim));
        step(e0, t, p, (t & 7) == 0);
        p ^= 1;
        e0 = e1; e1 = e2; e2 = e3; e3 = e4;
        e4 = e5; e5 = e6; e6 = e7; e7 = nn;
    }
    // final buffer parity: lim steps total from parity 0
    const int pf = lim & 1;

    __syncwarp();                          // compiler+HW fence before plain reads

    // log_Z = C + log(sum u)   (redundant per-lane; identical result)
    float s = 0.f;
    const float4* uf = reinterpret_cast<const float4*>(&u_sh[w][pf][0]);
#pragma unroll
    for (int q = 0; q < KK / 4; q++) {
        float4 uu = uf[q];
        s += (uu.x + uu.y) + (uu.z + uu.w);
    }
    float logz = C + __logf(s);

    // numerator: emission + transition scores along the gold path (masked)
    float num = 0.f;
    for (int tt = l; tt < Tn; tt += 32) {
        int yt = y_sh[w][tt];
        if (yt != 0) {
            num += eb[(size_t)tt * KK + yt];
            if (tt > 0) num += tr[y_sh[w][tt - 1] * KK + yt];
        }
    }
#pragma unroll
    for (int o = 16; o > 0; o >>= 1) num += __shfl_xor_sync(0xffffffffu, num, o);
    if (l == 0) g_ll[b] = num - logz;
}

__global__ void crf_finalize(float* __restrict__ out, int B)
{
    __shared__ float sh[8];
    int tid = threadIdx.x;
    float v = 0.f;
    for (int i = tid; i < B; i += blockDim.x) v += g_ll[i];
#pragma unroll
    for (int o = 16; o > 0; o >>= 1) v += __shfl_xor_sync(0xffffffffu, v, o);
    if ((tid & 31) == 0) sh[tid >> 5] = v;
    __syncthreads();
    if (tid == 0) {
        float s = 0.f;
#pragma unroll
        for (int w = 0; w < 8; w++) s += sh[w];
        out[0] = -s / (float)B;
    }
}

extern "C" void kernel_launch(void* const* d_in, const int* in_sizes, int n_in,
                              void* d_out, int out_size)
{
    const int*   y  = (const int*)d_in[0];
    const float* em = (const float*)d_in[1];
    const float* tr = (const float*)d_in[2];

    const int Tn = 1024;                 // problem shape: B=256, T=1024, K=64
    const int B  = in_sizes[0] / Tn;

    crf_forward_kernel<<<B / 2, 64>>>(y, em, tr, Tn);
    crf_finalize<<<1, 256>>>((float*)d_out, B);
}

// round 8
// speedup vs baseline: 1.7378x; 1.1314x over previous
#include <cuda_runtime.h>
#include <cstdint>

#define KK 64

__device__ __forceinline__ float fast_rcp(float x) {
    float r; asm("rcp.approx.f32 %0, %1;" : "=f"(r) : "f"(x)); return r;
}

__device__ __forceinline__ uint32_t smem_u32(const void* p) {
    uint32_t a;
    asm("{ .reg .u64 t; cvta.to.shared.u64 t, %1; cvt.u32.u64 %0, t; }"
        : "=r"(a) : "l"(p));
    return a;
}

// ONE BLOCK (2 warps, 64 threads) PER BATCH. Thread s owns state s.
// Per-warp FMA2 issue halved vs 1-warp layout (32 FMA2/lane); one
// __syncthreads per step is the only cross-warp coupling.
// Branchless scaled-exp recursion, packed f32x2 dots, compile-time parity:
//   u_t = (u_{t-1} . M) * exp(emit_t)        (masked steps: u_t = u_{t-1})
//   every 8th step (unconditional): u *= 1/u[0], C += log(u[0])
//   log_Z = C + log(sum_j u_T[j])
__global__ __launch_bounds__(KK, 1) void crf_forward_kernel(
    const int* __restrict__ y, const float* __restrict__ em,
    const float* __restrict__ tr, int Tn, float negInvB,
    float* __restrict__ out)
{
    __shared__ __align__(16) float u_sh[2][KK];      // [buf][state]
    __shared__ int y_sh[1024];                       // T = 1024
    __shared__ float red2[2];

    const int s = threadIdx.x;           // state index 0..63
    const int l = threadIdx.x & 31;
    const int b = blockIdx.x;
    const int* yb = y + (size_t)b * Tn;
    const float* eb = em + (size_t)b * Tn * KK;

    // Packed M row for this thread's single output state:
    //   Mp[q] = (exp(tr[2q][s]), exp(tr[2q+1][s]))
    unsigned long long Mp[32];
#pragma unroll
    for (int q = 0; q < 32; q++) {
        float m0 = __expf(tr[(2 * q) * KK + s]);
        float m1 = __expf(tr[(2 * q + 1) * KK + s]);
        asm("mov.b64 %0, {%1, %2};" : "=l"(Mp[q]) : "f"(m0), "f"(m1));
    }

    // stage y row in shared (cooperative)
    for (int t = s; t < Tn; t += KK) y_sh[t] = yb[t];

    // u0 = exp(emissions[b,0,:]); own value kept in a register too
    float uown = __expf(eb[s]);
    u_sh[0][s] = uown;
    float C = 0.f;
    __syncthreads();

    const uint32_t ubase = smem_u32(&u_sh[0][0]);
    const uint32_t ustore = ubase + (uint32_t)(s << 2);
    const float* ep = eb + s;

    // One recursion step. PSRC/RESC are compile-time in the hot loop.
    // Shared loads/stores are asm volatile: prevents cross-step CSE of the
    // textually-identical unrolled bodies (the R4/R5 bug) and pins ordering.
    auto step = [&](float ecur, int tt, int psrc, bool resc) {
        const int yt = y_sh[tt];
        float ex = __expf(ecur);
        float sc = 1.f;
        if (resc) {                       // unconditional rescale (valid always)
            float x0;
            asm volatile("ld.shared.f32 %0, [%1];"
                         : "=f"(x0) : "r"(ubase + (uint32_t)(psrc << 8)));
            sc = fast_rcp(x0);
            C += __logf(x0);
        }
        const float k = ex * sc;          // off the u-dependency chain
        const uint32_t ua = ubase + (uint32_t)(psrc << 8);
        unsigned long long A0 = 0, A1 = 0, A2 = 0, A3 = 0;
#pragma unroll
        for (int g = 0; g < 8; g++) {
            unsigned long long p0, p1, p2, p3;   // u[8g..8g+7] as 4 f32x2 pairs
            asm volatile("ld.shared.v2.u64 {%0, %1}, [%2];"
                : "=l"(p0), "=l"(p1) : "r"(ua + g * 32));
            asm volatile("ld.shared.v2.u64 {%0, %1}, [%2];"
                : "=l"(p2), "=l"(p3) : "r"(ua + g * 32 + 16));
            asm("fma.rn.f32x2 %0, %1, %2, %0;" : "+l"(A0) : "l"(p0), "l"(Mp[4 * g + 0]));
            asm("fma.rn.f32x2 %0, %1, %2, %0;" : "+l"(A1) : "l"(p1), "l"(Mp[4 * g + 1]));
            asm("fma.rn.f32x2 %0, %1, %2, %0;" : "+l"(A2) : "l"(p2), "l"(Mp[4 * g + 2]));
            asm("fma.rn.f32x2 %0, %1, %2, %0;" : "+l"(A3) : "l"(p3), "l"(Mp[4 * g + 3]));
        }
        asm("add.rn.f32x2 %0, %0, %1;" : "+l"(A0) : "l"(A2));
        asm("add.rn.f32x2 %0, %0, %1;" : "+l"(A1) : "l"(A3));
        asm("add.rn.f32x2 %0, %0, %1;" : "+l"(A0) : "l"(A1));
        float lo, hi;
        asm("mov.b64 {%0, %1}, %2;" : "=f"(lo), "=f"(hi) : "l"(A0));
        float dx = (lo + hi) * k;
        // branchless commit (no BSSY/BSYNC in the hot loop)
        uown = (yt != 0) ? dx : uown * sc;
        asm volatile("st.shared.f32 [%0], %1;"
                     :: "r"(ustore + (uint32_t)((psrc ^ 1) << 8)), "f"(uown));
        __syncthreads();
    };

    const int lim = Tn - 1;               // 1023
    auto eld = [&](int t) { return ep[(size_t)t * KK]; };

    // prefetch rows t .. t+7 (no clamps needed: lim >= 8 here)
    float e0 = eld(1), e1 = eld(2), e2 = eld(3), e3 = eld(4);
    float e4 = eld(5), e5 = eld(6), e6 = eld(7), e7 = eld(8);

    int t = 1;
    // main loop: t ≡ 1 (mod 8); parity at entry always 0; rescale at t+7 (≡0 mod 8)
    for (; t + 15 <= lim; t += 8) {
        float n0 = eld(t + 8),  n1 = eld(t + 9),  n2 = eld(t + 10), n3 = eld(t + 11);
        float n4 = eld(t + 12), n5 = eld(t + 13), n6 = eld(t + 14), n7 = eld(t + 15);
        step(e0, t,     0, false);
        step(e1, t + 1, 1, false);
        step(e2, t + 2, 0, false);
        step(e3, t + 3, 1, false);
        step(e4, t + 4, 0, false);
        step(e5, t + 5, 1, false);
        step(e6, t + 6, 0, false);
        step(e7, t + 7, 1, true);
        e0 = n0; e1 = n1; e2 = n2; e3 = n3;
        e4 = n4; e5 = n5; e6 = n6; e7 = n7;
    }

    // tail: runtime parity / rescale; shift-register prefetch with clamped loads
    int p = 0;                             // (t-1) is a multiple of 8 here
    for (; t <= lim; t++) {
        float nn = eld(min(t + 8, lim));
        step(e0, t, p, (t & 7) == 0);
        p ^= 1;
        e0 = e1; e1 = e2; e2 = e3; e3 = e4;
        e4 = e5; e5 = e6; e6 = e7; e7 = nn;
    }
    // final buffer parity: lim steps total from parity 0
    const int pf = lim & 1;

    // (last step ended with __syncthreads; u_sh[pf] is visible)

    // log_Z = C + log(sum u)   (redundant per-thread; identical result)
    float ssum = 0.f;
    const float4* uf = reinterpret_cast<const float4*>(&u_sh[pf][0]);
#pragma unroll
    for (int q = 0; q < KK / 4; q++) {
        float4 uu = uf[q];
        ssum += (uu.x + uu.y) + (uu.z + uu.w);
    }
    float logz = C + __logf(ssum);

    // numerator: emission + transition scores along the gold path (masked)
    float num = 0.f;
    for (int tt = s; tt < Tn; tt += KK) {
        int yt = y_sh[tt];
        if (yt != 0) {
            num += eb[(size_t)tt * KK + yt];
            if (tt > 0) num += tr[y_sh[tt - 1] * KK + yt];
        }
    }
#pragma unroll
    for (int o = 16; o > 0; o >>= 1) num += __shfl_xor_sync(0xffffffffu, num, o);
    if (l == 0) red2[s >> 5] = num;
    __syncthreads();
    if (s == 0) {
        float ll = (red2[0] + red2[1]) - logz;
        atomicAdd(out, ll * negInvB);      // out pre-zeroed via memsetAsync
    }
}

extern "C" void kernel_launch(void* const* d_in, const int* in_sizes, int n_in,
                              void* d_out, int out_size)
{
    const int*   y  = (const int*)d_in[0];
    const float* em = (const float*)d_in[1];
    const float* tr = (const float*)d_in[2];

    const int Tn = 1024;                 // problem shape: B=256, T=1024, K=64
    const int B  = in_sizes[0] / Tn;

    cudaMemsetAsync(d_out, 0, sizeof(float));
    crf_forward_kernel<<<B, KK>>>(y, em, tr, Tn, -1.0f / (float)B, (float*)d_out);
}